// round 10
// baseline (speedup 1.0000x reference)
#include <cuda_runtime.h>

// WeightedDiceLoss (sm_103a) — swizzled hsum ring, local 3-lane hsum producer,
// prefetch-pipelined refills, Rr=64 slabs for load balance.
// weight = 1 + 5*|boxavg31(target) - target|, zero pad, /961
// out = 1 - (2*sum(in*t*w) + 1) / (sum(in*w) + sum(t*w) + 1)

#define Wd    512
#define Hd    512
#define Rr    64
#define HALO  15
#define SLABR (Rr + 2*HALO)        // 94
#define RING  48
#define NCHUNK (Rr / 16)           // 4
#define INV_KK2 (1.0f/961.0f)

__device__ __forceinline__ int swz(int c) { return c ^ (((c >> 5) & 7) << 2); }

__device__ float g_part[3 * 1024];
__device__ unsigned int g_count = 0;

__global__ __launch_bounds__(512, 2)
void wdice_main(const float* __restrict__ input,
                const float* __restrict__ target,
                float* __restrict__ out)
{
    extern __shared__ float HS[];           // [RING][512] swizzled hsum rows
    const int tid  = threadIdx.x;
    const int wid  = tid >> 5;
    const int lane = tid & 31;
    const int img  = blockIdx.x >> 3;       // 8 slabs per image
    const int slab = blockIdx.x & 7;
    const int r0   = slab * Rr;
    const size_t imgOff = (size_t)img * (size_t)(Hd * Wd);

    // LDG target row (r0-15+pr+wid) into regs (zeros if out of range).
    auto pref = [&](int pr, float v[16]) {
        const int j  = pr + wid;
        const int gr = r0 - HALO + j;
        if (j < SLABR && gr >= 0 && gr < Hd) {
            const float4* row = (const float4*)(target + imgOff + (size_t)gr * Wd);
            #pragma unroll
            for (int q = 0; q < 4; q++) {
                float4 f = row[lane * 4 + q];
                v[4*q+0] = f.x; v[4*q+1] = f.y; v[4*q+2] = f.z; v[4*q+3] = f.w;
            }
        } else {
            #pragma unroll
            for (int i = 0; i < 16; i++) v[i] = 0.f;
        }
    };

    // Local-prefix hsum (window spans <=3 lanes) + swizzled STS.
    //   hsum[16L+i] = (T_{L-1} - p_{L-1}[i]) + T_L + p_{L+1}[i-1]
    auto scanStore = [&](int pr, float p[16]) {
        const int j = pr + wid;
        if (j >= SLABR) return;
        float4* dstRow = (float4*)(HS + (j % RING) * Wd);
        const int sL = (lane >> 1) & 7;
        #pragma unroll
        for (int i = 1; i < 16; i++) p[i] += p[i-1];
        const float T  = p[15];
        float Tp = __shfl_up_sync(0xffffffffu, T, 1);
        if (lane == 0) Tp = 0.f;
        const float base = Tp + T;
        float h[16];
        #pragma unroll
        for (int i = 0; i < 16; i++) {
            float pm = __shfl_up_sync(0xffffffffu, p[i], 1);
            if (lane == 0) pm = 0.f;
            h[i] = base - pm;
        }
        #pragma unroll
        for (int i = 1; i < 16; i++) {
            float pp = __shfl_down_sync(0xffffffffu, p[i-1], 1);
            if (lane == 31) pp = 0.f;
            h[i] += pp;
        }
        #pragma unroll
        for (int q = 0; q < 4; q++)
            dstRow[(4 * lane + q) ^ sL] =
                make_float4(h[4*q], h[4*q+1], h[4*q+2], h[4*q+3]);
    };

    // ---- Priming: rows 0..47 (two-buffer overlap), then prefetch rows 48..63.
    float pw[16];
    {
        float pa[16];
        pref(0,  pa);
        pref(16, pw);
        scanStore(0, pa);
        pref(32, pa);
        scanStore(16, pw);
        pref(48, pw);                    // refill data for after chunk 0
        scanStore(32, pa);
    }
    __syncthreads();

    // ---- Consumer: thread = column c.
    const int c  = tid;
    const int qc = swz(c);
    float vsum = 0.f;
    #pragma unroll
    for (int j = 0; j <= 2 * HALO; j++)
        vsum += HS[j * Wd + qc];

    float aI = 0.f, aA = 0.f, aB = 0.f;
    const float* inp = input  + imgOff + (size_t)r0 * Wd + c;
    const float* tgt = target + imgOff + (size_t)r0 * Wd + c;

    #pragma unroll
    for (int ch = 0; ch < NCHUNK; ch++) {
        #pragma unroll
        for (int kk = 0; kk < 16; kk++) {
            const int k = ch * 16 + kk;
            const int jAdd = ((k + 31) % RING) * Wd;
            const int jSub = (k % RING) * Wd;

            const float t  = tgt[k * Wd];
            const float in = inp[k * Wd];
            const float w  = fmaf(5.f, fabsf(fmaf(vsum, INV_KK2, -t)), 1.f);
            const float tw = t * w;
            aI = fmaf(in, tw, aI);
            aA = fmaf(in, w,  aA);
            aB += tw;

            if (k < Rr - 1)
                vsum += (HS[jAdd + qc] - HS[jSub + qc]);
        }
        __syncthreads();                     // rows ch*16..+15 dead
        if (ch < NCHUNK - 1) {
            scanStore(48 + ch * 16, pw);     // LDG issued one chunk ago
            if (ch < NCHUNK - 2)
                pref(48 + (ch + 1) * 16, pw);   // hide behind next consume
            __syncthreads();
        }
    }

    // ---- Block reduction (fixed order -> deterministic)
    #pragma unroll
    for (int o = 16; o > 0; o >>= 1) {
        aI += __shfl_down_sync(0xffffffffu, aI, o);
        aA += __shfl_down_sync(0xffffffffu, aA, o);
        aB += __shfl_down_sync(0xffffffffu, aB, o);
    }
    if (lane == 0) { HS[wid] = aI; HS[16 + wid] = aA; HS[32 + wid] = aB; }
    __syncthreads();
    __shared__ unsigned int sIsLast;
    if (tid == 0) {
        float I = 0.f, A = 0.f, B = 0.f;
        #pragma unroll
        for (int i = 0; i < 16; i++) { I += HS[i]; A += HS[16 + i]; B += HS[32 + i]; }
        g_part[blockIdx.x * 3 + 0] = I;
        g_part[blockIdx.x * 3 + 1] = A;
        g_part[blockIdx.x * 3 + 2] = B;
        __threadfence();
        sIsLast = (atomicAdd(&g_count, 1u) == gridDim.x - 1u);
    }
    __syncthreads();

    if (sIsLast) {
        const int nb = gridDim.x;
        float i = 0.f, a = 0.f, b = 0.f;
        for (int j = tid; j < nb; j += 512) {
            i += g_part[3 * j + 0];
            a += g_part[3 * j + 1];
            b += g_part[3 * j + 2];
        }
        #pragma unroll
        for (int o = 16; o > 0; o >>= 1) {
            i += __shfl_down_sync(0xffffffffu, i, o);
            a += __shfl_down_sync(0xffffffffu, a, o);
            b += __shfl_down_sync(0xffffffffu, b, o);
        }
        __syncthreads();
        if (lane == 0) { HS[wid] = i; HS[16 + wid] = a; HS[32 + wid] = b; }
        __syncthreads();
        if (tid == 0) {
            float I = 0.f, A = 0.f, B = 0.f;
            #pragma unroll
            for (int q = 0; q < 16; q++) { I += HS[q]; A += HS[16 + q]; B += HS[32 + q]; }
            out[0] = 1.f - (2.f * I + 1.f) / (A + B + 1.f);
            g_count = 0;
        }
    }
}

extern "C" void kernel_launch(void* const* d_in, const int* in_sizes, int n_in,
                              void* d_out, int out_size)
{
    const float* input  = (const float*)d_in[0];
    const float* target = (const float*)d_in[1];
    const int nImg = in_sizes[0] / (Hd * Wd);
    const int grid = nImg * (Hd / Rr);              // 512
    const size_t smem = (size_t)RING * Wd * sizeof(float);   // 98304 B

    cudaFuncSetAttribute(wdice_main,
                         cudaFuncAttributeMaxDynamicSharedMemorySize, (int)smem);
    wdice_main<<<grid, 512, smem>>>(input, target, (float*)d_out);
}